// round 14
// baseline (speedup 1.0000x reference)
#include <cuda_runtime.h>
#include <cuda_fp16.h>
#include <cstdint>
#include <math.h>

// ---------------- problem constants ----------------
constexpr int B_  = 2;
constexpr int C_  = 64;
constexpr int H_  = 256;
constexpr int W_  = 1216;
constexpr int HW_ = H_ * W_;        // 311296
constexpr int NP  = B_ * HW_;       // 622592
constexpr int NCH = 78;
constexpr int ITERS = 6;

// fp32 planes: 0-5 mask, 6 BASE set0, 7 BASE set1, 8-10 A{7,5,3} set0, 11-13 set1
__device__ float  g_scratch[(size_t)14 * NP];
// fp16 planes: 0-47 aff, 48-53 att7, 54-59 att5, 60-65 att3, 66-71 att1,
// 72 SA7, 73 SA5, 74 SA3, 75 T7, 76 T5, 77 T3
__device__ __half g_h[(size_t)78 * NP];
__device__ float  g_wpack[NCH * 576];
__device__ float  g_bpack[NCH];
__device__ uint2  g_wfrag[36 * 10 * 32];

__device__ __forceinline__ float sigf(float x) { return 1.0f / (1.0f + expf(-x)); }

// ---------------- weight packing ----------------
__global__ void pack_weights(
    const float* __restrict__ w7,  const float* __restrict__ s7,  const float* __restrict__ b7,
    const float* __restrict__ w5,  const float* __restrict__ s5,  const float* __restrict__ b5,
    const float* __restrict__ w3,  const float* __restrict__ s3,  const float* __restrict__ b3,
    const float* __restrict__ wa7, const float* __restrict__ sa7, const float* __restrict__ ba7,
    const float* __restrict__ wa5, const float* __restrict__ sa5, const float* __restrict__ ba5,
    const float* __restrict__ wa3, const float* __restrict__ sa3, const float* __restrict__ ba3,
    const float* __restrict__ wa1, const float* __restrict__ sa1, const float* __restrict__ ba1,
    const float* __restrict__ wm,  const float* __restrict__ sm,  const float* __restrict__ bm)
{
    int idx = blockIdx.x * blockDim.x + threadIdx.x;
    if (idx >= NCH * 576) return;
    int ch = idx / 576;
    int e  = idx - ch * 576;
    const float *w, *s, *b; int lc;
    if      (ch < 24) { w = w7;  s = s7;  b = b7;  lc = ch;      }
    else if (ch < 40) { w = w5;  s = s5;  b = b5;  lc = ch - 24; }
    else if (ch < 48) { w = w3;  s = s3;  b = b3;  lc = ch - 40; }
    else if (ch < 54) { w = wa7; s = sa7; b = ba7; lc = ch - 48; }
    else if (ch < 60) { w = wa5; s = sa5; b = ba5; lc = ch - 54; }
    else if (ch < 66) { w = wa3; s = sa3; b = ba3; lc = ch - 60; }
    else if (ch < 72) { w = wa1; s = sa1; b = ba1; lc = ch - 66; }
    else              { w = wm;  s = sm;  b = bm;  lc = ch - 72; }
    g_wpack[idx] = w[lc * 576 + e] * s[lc];
    if (e == 0) g_bpack[ch] = b[lc];
}

// ---------------- pre-linearize weights into mma b-fragment order ----------------
__global__ void pack_frags()
{
    int idx = blockIdx.x * 256 + threadIdx.x;
    if (idx >= 36 * 10 * 32) return;
    int lane = idx & 31;
    int nf   = (idx >> 5) % 10;
    int s    = idx / 320;
    int tap  = s >> 2;
    int kc   = s & 3;
    int n    = nf * 8 + (lane >> 2);
    int t4   = lane & 3;
    unsigned regs[2];
    #pragma unroll
    for (int r8 = 0; r8 < 2; ++r8) {
        int ci0 = kc * 16 + t4 * 2 + r8 * 8;
        float v0 = 0.f, v1 = 0.f;
        if (n < NCH) {
            v0 = g_wpack[n * 576 + ci0 * 9 + tap];
            v1 = g_wpack[n * 576 + (ci0 + 1) * 9 + tap];
        }
        unsigned lo = __half_as_ushort(__float2half(v0));
        unsigned hi = __half_as_ushort(__float2half(v1));
        regs[r8] = (hi << 16) | lo;
    }
    g_wfrag[idx] = make_uint2(regs[0], regs[1]);
}

// ---------------- tensor-core conv (R4 config) + fused it0 prep ----------------
constexpr int F_BYTES = 6 * 132 * 64 * 2;             // 101376
constexpr int WF_U2   = 36 * 10 * 32;                 // 11520 uint2
constexpr int CONV_SMEM = F_BYTES + WF_U2 * 8;        // 193536

__device__ __forceinline__ void mma16816(float* d, const unsigned* a, uint2 b)
{
    asm volatile(
        "mma.sync.aligned.m16n8k16.row.col.f32.f16.f16.f32 "
        "{%0,%1,%2,%3}, {%4,%5,%6,%7}, {%8,%9}, {%0,%1,%2,%3};"
        : "+f"(d[0]), "+f"(d[1]), "+f"(d[2]), "+f"(d[3])
        : "r"(a[0]), "r"(a[1]), "r"(a[2]), "r"(a[3]), "r"(b.x), "r"(b.y));
}

__device__ __forceinline__ void ldsm_x4(unsigned* a, unsigned addr)
{
    asm volatile(
        "ldmatrix.sync.aligned.m8n8.x4.shared.b16 {%0,%1,%2,%3}, [%4];"
        : "=r"(a[0]), "=r"(a[1]), "=r"(a[2]), "=r"(a[3]) : "r"(addr));
}

__global__ void __launch_bounds__(512, 1) conv_kernel(
    const float* __restrict__ feat, const float* __restrict__ d00,
    const float* __restrict__ d0)
{
    extern __shared__ char smem[];
    half*  F   = (half*)smem;
    uint2* wsh = (uint2*)(smem + F_BYTES);

    const int tid = threadIdx.x;
    const int bx  = blockIdx.x;
    const int x0  = (bx < 9) ? bx * 128 : (W_ - 128);
    const int y0  = blockIdx.y * 4;
    const int bb  = blockIdx.z;

    for (int idx = tid; idx < 6 * 130 * 32; idx += 512) {
        int xx  = idx % 130;
        int rem = idx / 130;
        int t2  = rem & 31;
        int yy  = rem >> 5;
        int c   = t2 * 2;
        int gy  = y0 - 1 + yy;
        int gx  = x0 - 1 + xx;
        float v0 = 0.f, v1 = 0.f;
        if ((unsigned)gy < (unsigned)H_ && (unsigned)gx < (unsigned)W_) {
            size_t base = ((size_t)(bb * 64 + c) * H_ + gy) * W_ + gx;
            v0 = __ldg(&feat[base]);
            v1 = __ldg(&feat[base + (size_t)HW_]);
        }
        unsigned lo = __half_as_ushort(__float2half(v0));
        unsigned hi = __half_as_ushort(__float2half(v1));
        int u = (c >> 3) ^ (xx & 7);
        int hidx = (yy * 132 + xx) * 64 + u * 8 + (c & 7);
        *reinterpret_cast<unsigned*>((char*)F + hidx * 2) = (hi << 16) | lo;
    }
    for (int idx = tid; idx < WF_U2; idx += 512)
        wsh[idx] = __ldg(&g_wfrag[idx]);
    __syncthreads();

    const int w     = tid >> 5;
    const int lane  = tid & 31;
    const int rowl  = w >> 2;
    const int xwarp = (w & 3) * 32;
    const int q     = lane >> 2;
    const int t4    = lane & 3;
    const int jrow  = ((lane >> 3) & 1) * 8 + (lane & 7);
    const int jhalf = lane >> 4;

    unsigned Fb;
    {
        unsigned long long gp = (unsigned long long)__cvta_generic_to_shared(F);
        Fb = (unsigned)gp;
    }

    float C[2][10][4];
    #pragma unroll
    for (int mf = 0; mf < 2; ++mf)
        #pragma unroll
        for (int nf = 0; nf < 10; ++nf)
            #pragma unroll
            for (int j = 0; j < 4; ++j) C[mf][nf][j] = 0.0f;

    #pragma unroll 1
    for (int tap = 0; tap < 9; ++tap) {
        const int ky = tap / 3;
        const int kx = tap - ky * 3;
        unsigned pb[2]; int xk[2];
        #pragma unroll
        for (int mf = 0; mf < 2; ++mf) {
            int xx = xwarp + mf * 16 + jrow + kx;
            xk[mf] = (xx & 7) << 4;
            pb[mf] = Fb + (((rowl + ky) * 132 + xx) << 7);
        }
        #pragma unroll
        for (int kc = 0; kc < 4; ++kc) {
            unsigned a0[4], a1[4];
            const int ubase = (kc * 2 + jhalf) << 4;
            ldsm_x4(a0, pb[0] + (ubase ^ xk[0]));
            ldsm_x4(a1, pb[1] + (ubase ^ xk[1]));
            const uint2* brow = wsh + (size_t)(tap * 4 + kc) * 320 + lane;
            #pragma unroll
            for (int nf = 0; nf < 10; ++nf) {
                uint2 b = brow[nf * 32];
                mma16816(C[0][nf], a0, b);
                mma16816(C[1][nf], a1, b);
            }
        }
    }

    // ---- epilogue: bias/act, fp16 stores, group sums, fused it0 A/BASE (fp32) ----
    #pragma unroll
    for (int mf = 0; mf < 2; ++mf) {
        #pragma unroll
        for (int r8 = 0; r8 < 2; ++r8) {
            const int x = x0 + xwarp + mf * 16 + q + r8 * 8;
            const int y = y0 + rowl;
            const int p = bb * HW_ + y * W_ + x;
            const float vld = (d00[p] > 0.0f) ? 1.0f : 0.0f;

            float s7 = 0.f, t7 = 0.f, s5 = 0.f, t5 = 0.f, s3 = 0.f, t3 = 0.f;
            float att_keep = 0.f;
            #pragma unroll
            for (int nf = 0; nf < 10; ++nf) {
                #pragma unroll
                for (int j = 0; j < 2; ++j) {
                    const int ch = nf * 8 + t4 * 2 + j;
                    if (ch >= NCH) continue;
                    float v = C[mf][nf][r8 * 2 + j] + __ldg(&g_bpack[ch]);
                    if (ch < 48) {
                        half hv = __float2half(v);
                        float vr = __half2float(hv);
                        if (ch < 24)      { s7 += fabsf(vr); t7 += vr; }
                        else if (ch < 40) { s5 += fabsf(vr); t5 += vr; }
                        else              { s3 += fabsf(vr); t3 += vr; }
                        g_h[(size_t)ch * NP + p] = hv;
                    } else {
                        v = sigf(v);
                        if (ch >= 72) {
                            v *= vld;
                            g_scratch[(size_t)(ch - 72) * NP + p] = v;
                        } else {
                            g_h[(size_t)ch * NP + p] = __float2half(v);
                            if (ch == 48 || ch == 54 || ch == 60 || ch == 66) att_keep = v;
                        }
                    }
                }
            }
            #pragma unroll
            for (int d = 1; d <= 2; d <<= 1) {
                s7 += __shfl_xor_sync(0xffffffffu, s7, d);
                t7 += __shfl_xor_sync(0xffffffffu, t7, d);
                s5 += __shfl_xor_sync(0xffffffffu, s5, d);
                t5 += __shfl_xor_sync(0xffffffffu, t5, d);
                s3 += __shfl_xor_sync(0xffffffffu, s3, d);
                t3 += __shfl_xor_sync(0xffffffffu, t3, d);
            }
            const int lb = lane & ~3;
            float a7v = __shfl_sync(0xffffffffu, att_keep, lb + 0);
            float a1v = __shfl_sync(0xffffffffu, att_keep, lb + 1);
            float a3v = __shfl_sync(0xffffffffu, att_keep, lb + 2);
            float a5v = __shfl_sync(0xffffffffu, att_keep, lb + 3);
            if (t4 == 0) {
                g_h[(size_t)72 * NP + p] = __float2half(s7);
                g_h[(size_t)73 * NP + p] = __float2half(s5);
                g_h[(size_t)74 * NP + p] = __float2half(s3);
                g_h[(size_t)75 * NP + p] = __float2half(t7);
                g_h[(size_t)76 * NP + p] = __float2half(t5);
                g_h[(size_t)77 * NP + p] = __float2half(t3);
                float denom = fmaf(a7v, s7, fmaf(a5v, s5, fmaf(a3v, s3, a1v)));
                float invd  = 1.0f / denom;
                float sumg  = invd * fmaf(a7v, t7, fmaf(a5v, t5, fmaf(a3v, t3, a1v)));
                float dv = d0[p];
                float m  = invd * dv;
                g_scratch[(size_t)8  * NP + p] = a7v * m;
                g_scratch[(size_t)9  * NP + p] = a5v * m;
                g_scratch[(size_t)10 * NP + p] = a3v * m;
                g_scratch[(size_t)6  * NP + p] = (1.0f - sumg) * dv + a1v * m;
            }
        }
    }
}

// ---------------- fused iteration (1 px/thread, fp16 aff, fp32 A-planes) ----------------
__device__ __constant__ const int G7DY[24] = {3,3,3,3,3,3,3, 2,2, 1,1, 0,0, -1,-1, -2,-2, -3,-3,-3,-3,-3,-3,-3};
__device__ __constant__ const int G7DX[24] = {3,2,1,0,-1,-2,-3, 3,-3, 3,-3, 3,-3, 3,-3, 3,-3, 3,2,1,0,-1,-2,-3};
__device__ __constant__ const int G5DY[16] = {2,2,2,2,2, 1,1, 0,0, -1,-1, -2,-2,-2,-2,-2};
__device__ __constant__ const int G5DX[16] = {2,1,0,-1,-2, 2,-2, 2,-2, 2,-2, 2,1,0,-1,-2};
__device__ __constant__ const int G3DY[8]  = {1,1,1, 0,0, -1,-1,-1};
__device__ __constant__ const int G3DX[8]  = {1,0,-1, 1,-1, 1,0,-1};

template <bool LAST>
__global__ void iter_fused(const float* __restrict__ d00, const float* __restrict__ d0,
                           float* __restrict__ out, int it, int rA, int wA,
                           int rBASE, int wBASE)
{
    int p = blockIdx.x * 256 + threadIdx.x;
    if (p >= NP) return;
    unsigned up = (unsigned)p;
    int b = up / (unsigned)HW_;
    unsigned r = up - (unsigned)b * HW_;
    int y = r / (unsigned)W_;
    int x = r - (unsigned)y * W_;

    const __half* AF  = g_h;
    const float* A7p = g_scratch + (size_t)(rA + 0) * NP;
    const float* A5p = g_scratch + (size_t)(rA + 1) * NP;
    const float* A3p = g_scratch + (size_t)(rA + 2) * NP;

    float acc = g_scratch[(size_t)rBASE * NP + p];

    const bool interior = (y >= 3) & (y < H_ - 3) & (x >= 3) & (x < W_ - 3);
    if (interior) {
        #pragma unroll
        for (int t = 0; t < 24; ++t) {
            int q = p + G7DY[t] * W_ + G7DX[t];
            acc = fmaf(__half2float(AF[(size_t)t * NP + q]), A7p[q], acc);
        }
        #pragma unroll
        for (int t = 0; t < 16; ++t) {
            int q = p + G5DY[t] * W_ + G5DX[t];
            acc = fmaf(__half2float(AF[(size_t)(24 + t) * NP + q]), A5p[q], acc);
        }
        #pragma unroll
        for (int t = 0; t < 8; ++t) {
            int q = p + G3DY[t] * W_ + G3DX[t];
            acc = fmaf(__half2float(AF[(size_t)(40 + t) * NP + q]), A3p[q], acc);
        }
    } else {
        #pragma unroll
        for (int t = 0; t < 24; ++t) {
            const int dy = G7DY[t], dx = G7DX[t];
            if ((unsigned)(y + dy) < (unsigned)H_ && (unsigned)(x + dx) < (unsigned)W_) {
                int q = p + dy * W_ + dx;
                acc = fmaf(__half2float(AF[(size_t)t * NP + q]), A7p[q], acc);
            }
        }
        #pragma unroll
        for (int t = 0; t < 16; ++t) {
            const int dy = G5DY[t], dx = G5DX[t];
            if ((unsigned)(y + dy) < (unsigned)H_ && (unsigned)(x + dx) < (unsigned)W_) {
                int q = p + dy * W_ + dx;
                acc = fmaf(__half2float(AF[(size_t)(24 + t) * NP + q]), A5p[q], acc);
            }
        }
        #pragma unroll
        for (int t = 0; t < 8; ++t) {
            const int dy = G3DY[t], dx = G3DX[t];
            if ((unsigned)(y + dy) < (unsigned)H_ && (unsigned)(x + dx) < (unsigned)W_) {
                int q = p + dy * W_ + dx;
                acc = fmaf(__half2float(AF[(size_t)(40 + t) * NP + q]), A3p[q], acc);
            }
        }
    }

    float mask = g_scratch[(size_t)it * NP + p];
    float dt = mask * d00[p] + (1.0f - mask) * acc;

    if (LAST) {
        out[p] = dt;
    } else {
        const int nit = it + 1;
        float a7 = __half2float(g_h[(size_t)(48 + nit) * NP + p]);
        float a5 = __half2float(g_h[(size_t)(54 + nit) * NP + p]);
        float a3 = __half2float(g_h[(size_t)(60 + nit) * NP + p]);
        float a1 = __half2float(g_h[(size_t)(66 + nit) * NP + p]);
        float s7 = __half2float(g_h[(size_t)72 * NP + p]);
        float s5 = __half2float(g_h[(size_t)73 * NP + p]);
        float s3 = __half2float(g_h[(size_t)74 * NP + p]);
        float t7 = __half2float(g_h[(size_t)75 * NP + p]);
        float t5 = __half2float(g_h[(size_t)76 * NP + p]);
        float t3 = __half2float(g_h[(size_t)77 * NP + p]);

        float denom = fmaf(a7, s7, fmaf(a5, s5, fmaf(a3, s3, a1)));
        float invd  = 1.0f / denom;
        float sumg  = invd * fmaf(a7, t7, fmaf(a5, t5, fmaf(a3, t3, a1)));
        float m = invd * dt;
        g_scratch[(size_t)(wA + 0) * NP + p] = a7 * m;
        g_scratch[(size_t)(wA + 1) * NP + p] = a5 * m;
        g_scratch[(size_t)(wA + 2) * NP + p] = a3 * m;
        g_scratch[(size_t)wBASE * NP + p] = (1.0f - sumg) * d0[p] + a1 * m;
    }
}

// ---------------- launch ----------------
extern "C" void kernel_launch(void* const* d_in, const int* in_sizes, int n_in,
                              void* d_out, int out_size)
{
    const float* feat = (const float*)d_in[0];
    const float* d0   = (const float*)d_in[1];
    const float* d00  = (const float*)d_in[2];

    cudaFuncSetAttribute(conv_kernel, cudaFuncAttributeMaxDynamicSharedMemorySize,
                         CONV_SMEM);

    pack_weights<<<(NCH * 576 + 255) / 256, 256>>>(
        (const float*)d_in[3],  (const float*)d_in[4],  (const float*)d_in[5],
        (const float*)d_in[6],  (const float*)d_in[7],  (const float*)d_in[8],
        (const float*)d_in[9],  (const float*)d_in[10], (const float*)d_in[11],
        (const float*)d_in[12], (const float*)d_in[13], (const float*)d_in[14],
        (const float*)d_in[15], (const float*)d_in[16], (const float*)d_in[17],
        (const float*)d_in[18], (const float*)d_in[19], (const float*)d_in[20],
        (const float*)d_in[21], (const float*)d_in[22], (const float*)d_in[23],
        (const float*)d_in[24], (const float*)d_in[25], (const float*)d_in[26]);

    pack_frags<<<(36 * 10 * 32 + 255) / 256, 256>>>();

    conv_kernel<<<dim3(10, H_ / 4, B_), 512, CONV_SMEM>>>(feat, d00, d0);

    const int nblk = NP / 256;  // 2432 exact
    for (int it = 0; it < ITERS; ++it) {
        const int rA = 8 + (it & 1) * 3;
        const int wA = 8 + ((it + 1) & 1) * 3;
        const int rB = 6 + (it & 1);
        const int wB = 6 + ((it + 1) & 1);
        if (it == ITERS - 1)
            iter_fused<true><<<nblk, 256>>>(d00, d0, (float*)d_out, it, rA, wA, rB, wB);
        else
            iter_fused<false><<<nblk, 256>>>(d00, d0, nullptr, it, rA, wA, rB, wB);
    }
}

// round 16
// speedup vs baseline: 1.0549x; 1.0549x over previous
#include <cuda_runtime.h>
#include <cuda_fp16.h>
#include <cstdint>
#include <math.h>

// ---------------- problem constants ----------------
constexpr int B_  = 2;
constexpr int C_  = 64;
constexpr int H_  = 256;
constexpr int W_  = 1216;
constexpr int HW_ = H_ * W_;        // 311296
constexpr int NP  = B_ * HW_;       // 622592
constexpr int NCH = 78;
constexpr int ITERS = 6;

// fp32 planes: 0-5 mask, 6 BASE set0, 7 BASE set1
__device__ float  g_scratch[(size_t)8 * NP];
// fp16 planes: 0-47 aff, 48-53 att7, 54-59 att5, 60-65 att3, 66-71 att1,
// 72 SA7, 73 SA5, 74 SA3, 75 T7, 76 T5, 77 T3, 78-80 A{7,5,3} set0, 81-83 set1
__device__ __half g_h[(size_t)84 * NP];
__device__ float  g_wpack[NCH * 576];
__device__ float  g_bpack[NCH];
__device__ uint2  g_wfrag[36 * 10 * 32];

__device__ __forceinline__ float sigf(float x) { return 1.0f / (1.0f + expf(-x)); }

// ---- L2 evict_last via createpolicy + cache_hint (scalar-width legal form) ----
__device__ __forceinline__ uint64_t mk_policy_el() {
    uint64_t pol;
    asm("createpolicy.fractional.L2::evict_last.b64 %0, 1.0;" : "=l"(pol));
    return pol;
}
__device__ __forceinline__ __half2 ldg_el_h2(const __half* p, uint64_t pol) {
    unsigned v;
    asm volatile("ld.global.nc.L2::cache_hint.b32 %0, [%1], %2;"
                 : "=r"(v) : "l"(p), "l"(pol));
    return *reinterpret_cast<__half2*>(&v);
}
__device__ __forceinline__ float ldg_el_h(const __half* p, uint64_t pol) {
    unsigned short v;
    asm volatile("ld.global.nc.L2::cache_hint.b16 %0, [%1], %2;"
                 : "=h"(v) : "l"(p), "l"(pol));
    __half h = *reinterpret_cast<__half*>(&v);
    return __half2float(h);
}
__device__ __forceinline__ void stg_el_h(__half* p, __half v, uint64_t pol) {
    unsigned short u = *reinterpret_cast<unsigned short*>(&v);
    asm volatile("st.global.L2::cache_hint.b16 [%0], %1, %2;"
                 :: "l"(p), "h"(u), "l"(pol) : "memory");
}

// ---------------- weight packing ----------------
__global__ void pack_weights(
    const float* __restrict__ w7,  const float* __restrict__ s7,  const float* __restrict__ b7,
    const float* __restrict__ w5,  const float* __restrict__ s5,  const float* __restrict__ b5,
    const float* __restrict__ w3,  const float* __restrict__ s3,  const float* __restrict__ b3,
    const float* __restrict__ wa7, const float* __restrict__ sa7, const float* __restrict__ ba7,
    const float* __restrict__ wa5, const float* __restrict__ sa5, const float* __restrict__ ba5,
    const float* __restrict__ wa3, const float* __restrict__ sa3, const float* __restrict__ ba3,
    const float* __restrict__ wa1, const float* __restrict__ sa1, const float* __restrict__ ba1,
    const float* __restrict__ wm,  const float* __restrict__ sm,  const float* __restrict__ bm)
{
    int idx = blockIdx.x * blockDim.x + threadIdx.x;
    if (idx >= NCH * 576) return;
    int ch = idx / 576;
    int e  = idx - ch * 576;
    const float *w, *s, *b; int lc;
    if      (ch < 24) { w = w7;  s = s7;  b = b7;  lc = ch;      }
    else if (ch < 40) { w = w5;  s = s5;  b = b5;  lc = ch - 24; }
    else if (ch < 48) { w = w3;  s = s3;  b = b3;  lc = ch - 40; }
    else if (ch < 54) { w = wa7; s = sa7; b = ba7; lc = ch - 48; }
    else if (ch < 60) { w = wa5; s = sa5; b = ba5; lc = ch - 54; }
    else if (ch < 66) { w = wa3; s = sa3; b = ba3; lc = ch - 60; }
    else if (ch < 72) { w = wa1; s = sa1; b = ba1; lc = ch - 66; }
    else              { w = wm;  s = sm;  b = bm;  lc = ch - 72; }
    g_wpack[idx] = w[lc * 576 + e] * s[lc];
    if (e == 0) g_bpack[ch] = b[lc];
}

// ---------------- pre-linearize weights into mma b-fragment order ----------------
__global__ void pack_frags()
{
    int idx = blockIdx.x * 256 + threadIdx.x;
    if (idx >= 36 * 10 * 32) return;
    int lane = idx & 31;
    int nf   = (idx >> 5) % 10;
    int s    = idx / 320;
    int tap  = s >> 2;
    int kc   = s & 3;
    int n    = nf * 8 + (lane >> 2);
    int t4   = lane & 3;
    unsigned regs[2];
    #pragma unroll
    for (int r8 = 0; r8 < 2; ++r8) {
        int ci0 = kc * 16 + t4 * 2 + r8 * 8;
        float v0 = 0.f, v1 = 0.f;
        if (n < NCH) {
            v0 = g_wpack[n * 576 + ci0 * 9 + tap];
            v1 = g_wpack[n * 576 + (ci0 + 1) * 9 + tap];
        }
        unsigned lo = __half_as_ushort(__float2half(v0));
        unsigned hi = __half_as_ushort(__float2half(v1));
        regs[r8] = (hi << 16) | lo;
    }
    g_wfrag[idx] = make_uint2(regs[0], regs[1]);
}

// ---------------- tensor-core conv (R4 config) + fused it0 prep ----------------
constexpr int F_BYTES = 6 * 132 * 64 * 2;             // 101376
constexpr int WF_U2   = 36 * 10 * 32;                 // 11520 uint2
constexpr int CONV_SMEM = F_BYTES + WF_U2 * 8;        // 193536

__device__ __forceinline__ void mma16816(float* d, const unsigned* a, uint2 b)
{
    asm volatile(
        "mma.sync.aligned.m16n8k16.row.col.f32.f16.f16.f32 "
        "{%0,%1,%2,%3}, {%4,%5,%6,%7}, {%8,%9}, {%0,%1,%2,%3};"
        : "+f"(d[0]), "+f"(d[1]), "+f"(d[2]), "+f"(d[3])
        : "r"(a[0]), "r"(a[1]), "r"(a[2]), "r"(a[3]), "r"(b.x), "r"(b.y));
}

__device__ __forceinline__ void ldsm_x4(unsigned* a, unsigned addr)
{
    asm volatile(
        "ldmatrix.sync.aligned.m8n8.x4.shared.b16 {%0,%1,%2,%3}, [%4];"
        : "=r"(a[0]), "=r"(a[1]), "=r"(a[2]), "=r"(a[3]) : "r"(addr));
}

__global__ void __launch_bounds__(512, 1) conv_kernel(
    const float* __restrict__ feat, const float* __restrict__ d00,
    const float* __restrict__ d0)
{
    extern __shared__ char smem[];
    half*  F   = (half*)smem;
    uint2* wsh = (uint2*)(smem + F_BYTES);

    const int tid = threadIdx.x;
    const int bx  = blockIdx.x;
    const int x0  = (bx < 9) ? bx * 128 : (W_ - 128);
    const int y0  = blockIdx.y * 4;
    const int bb  = blockIdx.z;

    for (int idx = tid; idx < 6 * 130 * 32; idx += 512) {
        int xx  = idx % 130;
        int rem = idx / 130;
        int t2  = rem & 31;
        int yy  = rem >> 5;
        int c   = t2 * 2;
        int gy  = y0 - 1 + yy;
        int gx  = x0 - 1 + xx;
        float v0 = 0.f, v1 = 0.f;
        if ((unsigned)gy < (unsigned)H_ && (unsigned)gx < (unsigned)W_) {
            size_t base = ((size_t)(bb * 64 + c) * H_ + gy) * W_ + gx;
            v0 = __ldg(&feat[base]);
            v1 = __ldg(&feat[base + (size_t)HW_]);
        }
        unsigned lo = __half_as_ushort(__float2half(v0));
        unsigned hi = __half_as_ushort(__float2half(v1));
        int u = (c >> 3) ^ (xx & 7);
        int hidx = (yy * 132 + xx) * 64 + u * 8 + (c & 7);
        *reinterpret_cast<unsigned*>((char*)F + hidx * 2) = (hi << 16) | lo;
    }
    for (int idx = tid; idx < WF_U2; idx += 512)
        wsh[idx] = __ldg(&g_wfrag[idx]);
    __syncthreads();

    const int w     = tid >> 5;
    const int lane  = tid & 31;
    const int rowl  = w >> 2;
    const int xwarp = (w & 3) * 32;
    const int q     = lane >> 2;
    const int t4    = lane & 3;
    const int jrow  = ((lane >> 3) & 1) * 8 + (lane & 7);
    const int jhalf = lane >> 4;

    unsigned Fb;
    {
        unsigned long long gp = (unsigned long long)__cvta_generic_to_shared(F);
        Fb = (unsigned)gp;
    }

    float C[2][10][4];
    #pragma unroll
    for (int mf = 0; mf < 2; ++mf)
        #pragma unroll
        for (int nf = 0; nf < 10; ++nf)
            #pragma unroll
            for (int j = 0; j < 4; ++j) C[mf][nf][j] = 0.0f;

    #pragma unroll 1
    for (int tap = 0; tap < 9; ++tap) {
        const int ky = tap / 3;
        const int kx = tap - ky * 3;
        unsigned pb[2]; int xk[2];
        #pragma unroll
        for (int mf = 0; mf < 2; ++mf) {
            int xx = xwarp + mf * 16 + jrow + kx;
            xk[mf] = (xx & 7) << 4;
            pb[mf] = Fb + (((rowl + ky) * 132 + xx) << 7);
        }
        #pragma unroll
        for (int kc = 0; kc < 4; ++kc) {
            unsigned a0[4], a1[4];
            const int ubase = (kc * 2 + jhalf) << 4;
            ldsm_x4(a0, pb[0] + (ubase ^ xk[0]));
            ldsm_x4(a1, pb[1] + (ubase ^ xk[1]));
            const uint2* brow = wsh + (size_t)(tap * 4 + kc) * 320 + lane;
            #pragma unroll
            for (int nf = 0; nf < 10; ++nf) {
                uint2 b = brow[nf * 32];
                mma16816(C[0][nf], a0, b);
                mma16816(C[1][nf], a1, b);
            }
        }
    }

    // ---- epilogue: bias/act, fp16 stores (aff hinted evict_last), sums, it0 prep ----
    const uint64_t pol = mk_policy_el();
    #pragma unroll
    for (int mf = 0; mf < 2; ++mf) {
        #pragma unroll
        for (int r8 = 0; r8 < 2; ++r8) {
            const int x = x0 + xwarp + mf * 16 + q + r8 * 8;
            const int y = y0 + rowl;
            const int p = bb * HW_ + y * W_ + x;
            const float vld = (d00[p] > 0.0f) ? 1.0f : 0.0f;

            float s7 = 0.f, t7 = 0.f, s5 = 0.f, t5 = 0.f, s3 = 0.f, t3 = 0.f;
            float att_keep = 0.f;
            #pragma unroll
            for (int nf = 0; nf < 10; ++nf) {
                #pragma unroll
                for (int j = 0; j < 2; ++j) {
                    const int ch = nf * 8 + t4 * 2 + j;
                    if (ch >= NCH) continue;
                    float v = C[mf][nf][r8 * 2 + j] + __ldg(&g_bpack[ch]);
                    if (ch < 48) {
                        half hv = __float2half(v);
                        float vr = __half2float(hv);
                        if (ch < 24)      { s7 += fabsf(vr); t7 += vr; }
                        else if (ch < 40) { s5 += fabsf(vr); t5 += vr; }
                        else              { s3 += fabsf(vr); t3 += vr; }
                        stg_el_h(&g_h[(size_t)ch * NP + p], hv, pol);
                    } else {
                        v = sigf(v);
                        if (ch >= 72) {
                            v *= vld;
                            g_scratch[(size_t)(ch - 72) * NP + p] = v;
                        } else {
                            g_h[(size_t)ch * NP + p] = __float2half(v);
                            if (ch == 48 || ch == 54 || ch == 60 || ch == 66) att_keep = v;
                        }
                    }
                }
            }
            #pragma unroll
            for (int d = 1; d <= 2; d <<= 1) {
                s7 += __shfl_xor_sync(0xffffffffu, s7, d);
                t7 += __shfl_xor_sync(0xffffffffu, t7, d);
                s5 += __shfl_xor_sync(0xffffffffu, s5, d);
                t5 += __shfl_xor_sync(0xffffffffu, t5, d);
                s3 += __shfl_xor_sync(0xffffffffu, s3, d);
                t3 += __shfl_xor_sync(0xffffffffu, t3, d);
            }
            const int lb = lane & ~3;
            float a7v = __shfl_sync(0xffffffffu, att_keep, lb + 0);
            float a1v = __shfl_sync(0xffffffffu, att_keep, lb + 1);
            float a3v = __shfl_sync(0xffffffffu, att_keep, lb + 2);
            float a5v = __shfl_sync(0xffffffffu, att_keep, lb + 3);
            if (t4 == 0) {
                g_h[(size_t)72 * NP + p] = __float2half(s7);
                g_h[(size_t)73 * NP + p] = __float2half(s5);
                g_h[(size_t)74 * NP + p] = __float2half(s3);
                g_h[(size_t)75 * NP + p] = __float2half(t7);
                g_h[(size_t)76 * NP + p] = __float2half(t5);
                g_h[(size_t)77 * NP + p] = __float2half(t3);
                float denom = fmaf(a7v, s7, fmaf(a5v, s5, fmaf(a3v, s3, a1v)));
                float invd  = 1.0f / denom;
                float sumg  = invd * fmaf(a7v, t7, fmaf(a5v, t5, fmaf(a3v, t3, a1v)));
                float dv = d0[p];
                float m  = invd * dv;
                g_h[(size_t)78 * NP + p] = __float2half(a7v * m);
                g_h[(size_t)79 * NP + p] = __float2half(a5v * m);
                g_h[(size_t)80 * NP + p] = __float2half(a3v * m);
                g_scratch[(size_t)6 * NP + p] = (1.0f - sumg) * dv + a1v * m;
            }
        }
    }
}

// ---------------- fused iteration (2 px/thread, fp16 streams, evict_last aff) ----------------
__device__ __constant__ const int G7DY[24] = {3,3,3,3,3,3,3, 2,2, 1,1, 0,0, -1,-1, -2,-2, -3,-3,-3,-3,-3,-3,-3};
__device__ __constant__ const int G7DX[24] = {3,2,1,0,-1,-2,-3, 3,-3, 3,-3, 3,-3, 3,-3, 3,-3, 3,2,1,0,-1,-2,-3};
__device__ __constant__ const int G5DY[16] = {2,2,2,2,2, 1,1, 0,0, -1,-1, -2,-2,-2,-2,-2};
__device__ __constant__ const int G5DX[16] = {2,1,0,-1,-2, 2,-2, 2,-2, 2,-2, 2,1,0,-1,-2};
__device__ __constant__ const int G3DY[8]  = {1,1,1, 0,0, -1,-1,-1};
__device__ __constant__ const int G3DX[8]  = {1,0,-1, 1,-1, 1,0,-1};

template <bool LAST>
__global__ void iter_fused(const float* __restrict__ d00, const float* __restrict__ d0,
                           float* __restrict__ out, int it, int rA, int wA,
                           int rBASE, int wBASE)
{
    int idx = blockIdx.x * 256 + threadIdx.x;
    int p0 = idx * 2;
    if (p0 >= NP) return;
    unsigned up = (unsigned)p0;
    int b = up / (unsigned)HW_;
    unsigned r = up - (unsigned)b * HW_;
    int y  = r / (unsigned)W_;
    int x0 = r - (unsigned)y * W_;

    const __half* AF  = g_h;
    const __half* A7p = g_h + (size_t)(rA + 0) * NP;
    const __half* A5p = g_h + (size_t)(rA + 1) * NP;
    const __half* A3p = g_h + (size_t)(rA + 2) * NP;

    const uint64_t pol = mk_policy_el();

    float2 base = *reinterpret_cast<const float2*>(g_scratch + (size_t)rBASE * NP + p0);
    float acc0 = base.x, acc1 = base.y;

    const bool interior = (y >= 3) & (y < H_ - 3) & (x0 >= 3) & (x0 + 1 < W_ - 3);
    if (interior) {
        #pragma unroll
        for (int t = 0; t < 24; ++t) {
            const int dy = G7DY[t], dx = G7DX[t];
            int qq = p0 + dy * W_ + dx;
            const __half* fp = AF + (size_t)t * NP + qq;
            if ((dx & 1) == 0) {
                float2 f = __half22float2(ldg_el_h2(fp, pol));
                float2 a = __half22float2(*reinterpret_cast<const __half2*>(A7p + qq));
                acc0 = fmaf(f.x, a.x, acc0);
                acc1 = fmaf(f.y, a.y, acc1);
            } else {
                acc0 = fmaf(ldg_el_h(fp, pol),     __half2float(A7p[qq]),     acc0);
                acc1 = fmaf(ldg_el_h(fp + 1, pol), __half2float(A7p[qq + 1]), acc1);
            }
        }
        #pragma unroll
        for (int t = 0; t < 16; ++t) {
            const int dy = G5DY[t], dx = G5DX[t];
            int qq = p0 + dy * W_ + dx;
            const __half* fp = AF + (size_t)(24 + t) * NP + qq;
            if ((dx & 1) == 0) {
                float2 f = __half22float2(ldg_el_h2(fp, pol));
                float2 a = __half22float2(*reinterpret_cast<const __half2*>(A5p + qq));
                acc0 = fmaf(f.x, a.x, acc0);
                acc1 = fmaf(f.y, a.y, acc1);
            } else {
                acc0 = fmaf(ldg_el_h(fp, pol),     __half2float(A5p[qq]),     acc0);
                acc1 = fmaf(ldg_el_h(fp + 1, pol), __half2float(A5p[qq + 1]), acc1);
            }
        }
        #pragma unroll
        for (int t = 0; t < 8; ++t) {
            const int dy = G3DY[t], dx = G3DX[t];
            int qq = p0 + dy * W_ + dx;
            const __half* fp = AF + (size_t)(40 + t) * NP + qq;
            if ((dx & 1) == 0) {
                float2 f = __half22float2(ldg_el_h2(fp, pol));
                float2 a = __half22float2(*reinterpret_cast<const __half2*>(A3p + qq));
                acc0 = fmaf(f.x, a.x, acc0);
                acc1 = fmaf(f.y, a.y, acc1);
            } else {
                acc0 = fmaf(ldg_el_h(fp, pol),     __half2float(A3p[qq]),     acc0);
                acc1 = fmaf(ldg_el_h(fp + 1, pol), __half2float(A3p[qq + 1]), acc1);
            }
        }
    } else {
        #pragma unroll
        for (int px = 0; px < 2; ++px) {
            const int xx = x0 + px;
            const int pp = p0 + px;
            float acc = (px == 0) ? acc0 : acc1;
            #pragma unroll
            for (int t = 0; t < 24; ++t) {
                const int dy = G7DY[t], dx = G7DX[t];
                if ((unsigned)(y + dy) < (unsigned)H_ && (unsigned)(xx + dx) < (unsigned)W_) {
                    int qq = pp + dy * W_ + dx;
                    acc = fmaf(ldg_el_h(AF + (size_t)t * NP + qq, pol), __half2float(A7p[qq]), acc);
                }
            }
            #pragma unroll
            for (int t = 0; t < 16; ++t) {
                const int dy = G5DY[t], dx = G5DX[t];
                if ((unsigned)(y + dy) < (unsigned)H_ && (unsigned)(xx + dx) < (unsigned)W_) {
                    int qq = pp + dy * W_ + dx;
                    acc = fmaf(ldg_el_h(AF + (size_t)(24 + t) * NP + qq, pol), __half2float(A5p[qq]), acc);
                }
            }
            #pragma unroll
            for (int t = 0; t < 8; ++t) {
                const int dy = G3DY[t], dx = G3DX[t];
                if ((unsigned)(y + dy) < (unsigned)H_ && (unsigned)(xx + dx) < (unsigned)W_) {
                    int qq = pp + dy * W_ + dx;
                    acc = fmaf(ldg_el_h(AF + (size_t)(40 + t) * NP + qq, pol), __half2float(A3p[qq]), acc);
                }
            }
            if (px == 0) acc0 = acc; else acc1 = acc;
        }
    }

    float2 mk   = *reinterpret_cast<const float2*>(g_scratch + (size_t)it * NP + p0);
    float2 dd00 = *reinterpret_cast<const float2*>(d00 + p0);
    float dt0 = mk.x * dd00.x + (1.0f - mk.x) * acc0;
    float dt1 = mk.y * dd00.y + (1.0f - mk.y) * acc1;

    if (LAST) {
        *reinterpret_cast<float2*>(out + p0) = make_float2(dt0, dt1);
    } else {
        const int nit = it + 1;
        float2 a7 = __half22float2(*reinterpret_cast<const __half2*>(g_h + (size_t)(48 + nit) * NP + p0));
        float2 a5 = __half22float2(*reinterpret_cast<const __half2*>(g_h + (size_t)(54 + nit) * NP + p0));
        float2 a3 = __half22float2(*reinterpret_cast<const __half2*>(g_h + (size_t)(60 + nit) * NP + p0));
        float2 a1 = __half22float2(*reinterpret_cast<const __half2*>(g_h + (size_t)(66 + nit) * NP + p0));
        float2 s7 = __half22float2(ldg_el_h2(g_h + (size_t)72 * NP + p0, pol));
        float2 s5 = __half22float2(ldg_el_h2(g_h + (size_t)73 * NP + p0, pol));
        float2 s3 = __half22float2(ldg_el_h2(g_h + (size_t)74 * NP + p0, pol));
        float2 t7 = __half22float2(ldg_el_h2(g_h + (size_t)75 * NP + p0, pol));
        float2 t5 = __half22float2(ldg_el_h2(g_h + (size_t)76 * NP + p0, pol));
        float2 t3 = __half22float2(ldg_el_h2(g_h + (size_t)77 * NP + p0, pol));
        float2 dd0 = *reinterpret_cast<const float2*>(d0 + p0);

        float den0 = fmaf(a7.x, s7.x, fmaf(a5.x, s5.x, fmaf(a3.x, s3.x, a1.x)));
        float den1 = fmaf(a7.y, s7.y, fmaf(a5.y, s5.y, fmaf(a3.y, s3.y, a1.y)));
        float iv0 = 1.0f / den0, iv1 = 1.0f / den1;
        float sg0 = iv0 * fmaf(a7.x, t7.x, fmaf(a5.x, t5.x, fmaf(a3.x, t3.x, a1.x)));
        float sg1 = iv1 * fmaf(a7.y, t7.y, fmaf(a5.y, t5.y, fmaf(a3.y, t3.y, a1.y)));
        float m0 = iv0 * dt0, m1 = iv1 * dt1;

        *reinterpret_cast<__half2*>(g_h + (size_t)(wA + 0) * NP + p0) = __floats2half2_rn(a7.x * m0, a7.y * m1);
        *reinterpret_cast<__half2*>(g_h + (size_t)(wA + 1) * NP + p0) = __floats2half2_rn(a5.x * m0, a5.y * m1);
        *reinterpret_cast<__half2*>(g_h + (size_t)(wA + 2) * NP + p0) = __floats2half2_rn(a3.x * m0, a3.y * m1);
        float b0 = (1.0f - sg0) * dd0.x + a1.x * m0;
        float b1 = (1.0f - sg1) * dd0.y + a1.y * m1;
        *reinterpret_cast<float2*>(g_scratch + (size_t)wBASE * NP + p0) = make_float2(b0, b1);
    }
}

// ---------------- launch ----------------
extern "C" void kernel_launch(void* const* d_in, const int* in_sizes, int n_in,
                              void* d_out, int out_size)
{
    const float* feat = (const float*)d_in[0];
    const float* d0   = (const float*)d_in[1];
    const float* d00  = (const float*)d_in[2];

    cudaFuncSetAttribute(conv_kernel, cudaFuncAttributeMaxDynamicSharedMemorySize,
                         CONV_SMEM);

    pack_weights<<<(NCH * 576 + 255) / 256, 256>>>(
        (const float*)d_in[3],  (const float*)d_in[4],  (const float*)d_in[5],
        (const float*)d_in[6],  (const float*)d_in[7],  (const float*)d_in[8],
        (const float*)d_in[9],  (const float*)d_in[10], (const float*)d_in[11],
        (const float*)d_in[12], (const float*)d_in[13], (const float*)d_in[14],
        (const float*)d_in[15], (const float*)d_in[16], (const float*)d_in[17],
        (const float*)d_in[18], (const float*)d_in[19], (const float*)d_in[20],
        (const float*)d_in[21], (const float*)d_in[22], (const float*)d_in[23],
        (const float*)d_in[24], (const float*)d_in[25], (const float*)d_in[26]);

    pack_frags<<<(36 * 10 * 32 + 255) / 256, 256>>>();

    conv_kernel<<<dim3(10, H_ / 4, B_), 512, CONV_SMEM>>>(feat, d00, d0);

    const int nblk2 = NP / 512;  // 1216 exact
    for (int it = 0; it < ITERS; ++it) {
        const int rA = 78 + (it & 1) * 3;
        const int wA = 78 + ((it + 1) & 1) * 3;
        const int rB = 6 + (it & 1);
        const int wB = 6 + ((it + 1) & 1);
        if (it == ITERS - 1)
            iter_fused<true><<<nblk2, 256>>>(d00, d0, (float*)d_out, it, rA, wA, rB, wB);
        else
            iter_fused<false><<<nblk2, 256>>>(d00, d0, nullptr, it, rA, wA, rB, wB);
    }
}

// round 17
// speedup vs baseline: 1.1203x; 1.0620x over previous
#include <cuda_runtime.h>
#include <cuda_fp16.h>
#include <cstdint>
#include <math.h>

// ---------------- problem constants ----------------
constexpr int B_  = 2;
constexpr int C_  = 64;
constexpr int H_  = 256;
constexpr int W_  = 1216;
constexpr int HW_ = H_ * W_;        // 311296
constexpr int NP  = B_ * HW_;       // 622592
constexpr int NCH = 78;
constexpr int ITERS = 6;

// fp32 planes: 0-5 mask, 6 BASE set0, 7 BASE set1
__device__ float  g_scratch[(size_t)8 * NP];
// fp16 planes: 0-47 aff, 48-53 att7, 54-59 att5, 60-65 att3, 66-71 att1,
// 72 SA7, 73 SA5, 74 SA3, 75 T7, 76 T5, 77 T3, 78-80 A{7,5,3} set0, 81-83 set1
__device__ __half g_h[(size_t)84 * NP];
__device__ float  g_wpack[NCH * 576];
__device__ float  g_bpack[NCH];
__device__ uint2  g_wfrag[36 * 10 * 32];

__device__ __forceinline__ float sigf(float x) { return 1.0f / (1.0f + expf(-x)); }

// ---------------- weight packing ----------------
__global__ void pack_weights(
    const float* __restrict__ w7,  const float* __restrict__ s7,  const float* __restrict__ b7,
    const float* __restrict__ w5,  const float* __restrict__ s5,  const float* __restrict__ b5,
    const float* __restrict__ w3,  const float* __restrict__ s3,  const float* __restrict__ b3,
    const float* __restrict__ wa7, const float* __restrict__ sa7, const float* __restrict__ ba7,
    const float* __restrict__ wa5, const float* __restrict__ sa5, const float* __restrict__ ba5,
    const float* __restrict__ wa3, const float* __restrict__ sa3, const float* __restrict__ ba3,
    const float* __restrict__ wa1, const float* __restrict__ sa1, const float* __restrict__ ba1,
    const float* __restrict__ wm,  const float* __restrict__ sm,  const float* __restrict__ bm)
{
    int idx = blockIdx.x * blockDim.x + threadIdx.x;
    if (idx >= NCH * 576) return;
    int ch = idx / 576;
    int e  = idx - ch * 576;
    const float *w, *s, *b; int lc;
    if      (ch < 24) { w = w7;  s = s7;  b = b7;  lc = ch;      }
    else if (ch < 40) { w = w5;  s = s5;  b = b5;  lc = ch - 24; }
    else if (ch < 48) { w = w3;  s = s3;  b = b3;  lc = ch - 40; }
    else if (ch < 54) { w = wa7; s = sa7; b = ba7; lc = ch - 48; }
    else if (ch < 60) { w = wa5; s = sa5; b = ba5; lc = ch - 54; }
    else if (ch < 66) { w = wa3; s = sa3; b = ba3; lc = ch - 60; }
    else if (ch < 72) { w = wa1; s = sa1; b = ba1; lc = ch - 66; }
    else              { w = wm;  s = sm;  b = bm;  lc = ch - 72; }
    g_wpack[idx] = w[lc * 576 + e] * s[lc];
    if (e == 0) g_bpack[ch] = b[lc];
}

// ---------------- pre-linearize weights into mma b-fragment order ----------------
__global__ void pack_frags()
{
    int idx = blockIdx.x * 256 + threadIdx.x;
    if (idx >= 36 * 10 * 32) return;
    int lane = idx & 31;
    int nf   = (idx >> 5) % 10;
    int s    = idx / 320;
    int tap  = s >> 2;
    int kc   = s & 3;
    int n    = nf * 8 + (lane >> 2);
    int t4   = lane & 3;
    unsigned regs[2];
    #pragma unroll
    for (int r8 = 0; r8 < 2; ++r8) {
        int ci0 = kc * 16 + t4 * 2 + r8 * 8;
        float v0 = 0.f, v1 = 0.f;
        if (n < NCH) {
            v0 = g_wpack[n * 576 + ci0 * 9 + tap];
            v1 = g_wpack[n * 576 + (ci0 + 1) * 9 + tap];
        }
        unsigned lo = __half_as_ushort(__float2half(v0));
        unsigned hi = __half_as_ushort(__float2half(v1));
        regs[r8] = (hi << 16) | lo;
    }
    g_wfrag[idx] = make_uint2(regs[0], regs[1]);
}

// dummy kernels: shift conv to ncu capture slot 5
__global__ void noopk() {}

// ---------------- tensor-core conv: 4y x 64x CTA, 256 thr, 2 CTAs/SM ----------------
// F smem: [6 rows][68 x][64 ch] fp16, 16B-unit xor swizzle. B-frags staged in 2 kc-phases.
constexpr int FC_BYTES = 6 * 68 * 64 * 2;             // 52224
constexpr int WH_U2    = 18 * 320;                    // 5760 uint2 (one kc-phase)
constexpr int CONV_SMEM = FC_BYTES + WH_U2 * 8;       // 98304

__device__ __forceinline__ void mma16816(float* d, const unsigned* a, uint2 b)
{
    asm volatile(
        "mma.sync.aligned.m16n8k16.row.col.f32.f16.f16.f32 "
        "{%0,%1,%2,%3}, {%4,%5,%6,%7}, {%8,%9}, {%0,%1,%2,%3};"
        : "+f"(d[0]), "+f"(d[1]), "+f"(d[2]), "+f"(d[3])
        : "r"(a[0]), "r"(a[1]), "r"(a[2]), "r"(a[3]), "r"(b.x), "r"(b.y));
}

__device__ __forceinline__ void ldsm_x4(unsigned* a, unsigned addr)
{
    asm volatile(
        "ldmatrix.sync.aligned.m8n8.x4.shared.b16 {%0,%1,%2,%3}, [%4];"
        : "=r"(a[0]), "=r"(a[1]), "=r"(a[2]), "=r"(a[3]) : "r"(addr));
}

__global__ void __launch_bounds__(256, 2) conv_kernel(
    const float* __restrict__ feat, const float* __restrict__ d00,
    const float* __restrict__ d0)
{
    extern __shared__ char smem[];
    half*  F   = (half*)smem;
    uint2* wsh = (uint2*)(smem + FC_BYTES);

    const int tid = threadIdx.x;
    const int x0  = blockIdx.x * 64;        // 19 tiles exact
    const int y0  = blockIdx.y * 4;
    const int bb  = blockIdx.z;

    // feature tile: 6 rows x 66 cols x 64 ch -> fp16 channel-last swizzled
    for (int idx = tid; idx < 6 * 66 * 32; idx += 256) {
        int xx  = idx % 66;
        int rem = idx / 66;
        int t2  = rem & 31;
        int yy  = rem >> 5;
        int c   = t2 * 2;
        int gy  = y0 - 1 + yy;
        int gx  = x0 - 1 + xx;
        float v0 = 0.f, v1 = 0.f;
        if ((unsigned)gy < (unsigned)H_ && (unsigned)gx < (unsigned)W_) {
            size_t base = ((size_t)(bb * 64 + c) * H_ + gy) * W_ + gx;
            v0 = __ldg(&feat[base]);
            v1 = __ldg(&feat[base + (size_t)HW_]);
        }
        unsigned lo = __half_as_ushort(__float2half(v0));
        unsigned hi = __half_as_ushort(__float2half(v1));
        int u = (c >> 3) ^ (xx & 7);
        int hidx = (yy * 68 + xx) * 64 + u * 8 + (c & 7);
        *reinterpret_cast<unsigned*>((char*)F + hidx * 2) = (hi << 16) | lo;
    }
    // B-frag phase 0 (kc = 0,1)
    for (int i = tid; i < WH_U2; i += 256) {
        int l = i / 320, r = i - l * 320;
        int tap = l >> 1, kc = l & 1;
        wsh[i] = __ldg(&g_wfrag[(size_t)(tap * 4 + kc) * 320 + r]);
    }
    __syncthreads();

    const int w     = tid >> 5;
    const int lane  = tid & 31;
    const int rowl  = w >> 1;               // 0..3
    const int xwarp = (w & 1) * 32;         // 0 or 32
    const int q     = lane >> 2;
    const int t4    = lane & 3;
    const int jrow  = ((lane >> 3) & 1) * 8 + (lane & 7);
    const int jhalf = lane >> 4;

    unsigned Fb;
    {
        unsigned long long gp = (unsigned long long)__cvta_generic_to_shared(F);
        Fb = (unsigned)gp;
    }

    float C[2][10][4];
    #pragma unroll
    for (int mf = 0; mf < 2; ++mf)
        #pragma unroll
        for (int nf = 0; nf < 10; ++nf)
            #pragma unroll
            for (int j = 0; j < 4; ++j) C[mf][nf][j] = 0.0f;

    #pragma unroll 1
    for (int ph = 0; ph < 2; ++ph) {
        if (ph == 1) {
            __syncthreads();
            for (int i = tid; i < WH_U2; i += 256) {
                int l = i / 320, r = i - l * 320;
                int tap = l >> 1, kc = (l & 1) + 2;
                wsh[i] = __ldg(&g_wfrag[(size_t)(tap * 4 + kc) * 320 + r]);
            }
            __syncthreads();
        }
        #pragma unroll 1
        for (int tap = 0; tap < 9; ++tap) {
            const int ky = tap / 3;
            const int kx = tap - ky * 3;
            unsigned pb[2]; int xk[2];
            #pragma unroll
            for (int mf = 0; mf < 2; ++mf) {
                int xx = xwarp + mf * 16 + jrow + kx;
                xk[mf] = (xx & 7) << 4;
                pb[mf] = Fb + (((rowl + ky) * 68 + xx) << 7);
            }
            #pragma unroll
            for (int kcl = 0; kcl < 2; ++kcl) {
                const int kc = ph * 2 + kcl;
                unsigned a0[4], a1[4];
                const int ubase = (kc * 2 + jhalf) << 4;
                ldsm_x4(a0, pb[0] + (ubase ^ xk[0]));
                ldsm_x4(a1, pb[1] + (ubase ^ xk[1]));
                const uint2* brow = wsh + (size_t)(tap * 2 + kcl) * 320 + lane;
                #pragma unroll
                for (int nf = 0; nf < 10; ++nf) {
                    uint2 b = brow[nf * 32];
                    mma16816(C[0][nf], a0, b);
                    mma16816(C[1][nf], a1, b);
                }
            }
        }
    }

    // ---- epilogue: bias/act, fp16 stores, sums, fused it0 prep ----
    #pragma unroll
    for (int mf = 0; mf < 2; ++mf) {
        #pragma unroll
        for (int r8 = 0; r8 < 2; ++r8) {
            const int x = x0 + xwarp + mf * 16 + q + r8 * 8;
            const int y = y0 + rowl;
            const int p = bb * HW_ + y * W_ + x;
            const float vld = (d00[p] > 0.0f) ? 1.0f : 0.0f;

            float s7 = 0.f, t7 = 0.f, s5 = 0.f, t5 = 0.f, s3 = 0.f, t3 = 0.f;
            float att_keep = 0.f;
            #pragma unroll
            for (int nf = 0; nf < 10; ++nf) {
                #pragma unroll
                for (int j = 0; j < 2; ++j) {
                    const int ch = nf * 8 + t4 * 2 + j;
                    if (ch >= NCH) continue;
                    float v = C[mf][nf][r8 * 2 + j] + __ldg(&g_bpack[ch]);
                    if (ch < 48) {
                        half hv = __float2half(v);
                        float vr = __half2float(hv);
                        if (ch < 24)      { s7 += fabsf(vr); t7 += vr; }
                        else if (ch < 40) { s5 += fabsf(vr); t5 += vr; }
                        else              { s3 += fabsf(vr); t3 += vr; }
                        g_h[(size_t)ch * NP + p] = hv;
                    } else {
                        v = sigf(v);
                        if (ch >= 72) {
                            v *= vld;
                            g_scratch[(size_t)(ch - 72) * NP + p] = v;
                        } else {
                            g_h[(size_t)ch * NP + p] = __float2half(v);
                            if (ch == 48 || ch == 54 || ch == 60 || ch == 66) att_keep = v;
                        }
                    }
                }
            }
            #pragma unroll
            for (int d = 1; d <= 2; d <<= 1) {
                s7 += __shfl_xor_sync(0xffffffffu, s7, d);
                t7 += __shfl_xor_sync(0xffffffffu, t7, d);
                s5 += __shfl_xor_sync(0xffffffffu, s5, d);
                t5 += __shfl_xor_sync(0xffffffffu, t5, d);
                s3 += __shfl_xor_sync(0xffffffffu, s3, d);
                t3 += __shfl_xor_sync(0xffffffffu, t3, d);
            }
            const int lb = lane & ~3;
            float a7v = __shfl_sync(0xffffffffu, att_keep, lb + 0);
            float a1v = __shfl_sync(0xffffffffu, att_keep, lb + 1);
            float a3v = __shfl_sync(0xffffffffu, att_keep, lb + 2);
            float a5v = __shfl_sync(0xffffffffu, att_keep, lb + 3);
            if (t4 == 0) {
                g_h[(size_t)72 * NP + p] = __float2half(s7);
                g_h[(size_t)73 * NP + p] = __float2half(s5);
                g_h[(size_t)74 * NP + p] = __float2half(s3);
                g_h[(size_t)75 * NP + p] = __float2half(t7);
                g_h[(size_t)76 * NP + p] = __float2half(t5);
                g_h[(size_t)77 * NP + p] = __float2half(t3);
                float denom = fmaf(a7v, s7, fmaf(a5v, s5, fmaf(a3v, s3, a1v)));
                float invd  = 1.0f / denom;
                float sumg  = invd * fmaf(a7v, t7, fmaf(a5v, t5, fmaf(a3v, t3, a1v)));
                float dv = d0[p];
                float m  = invd * dv;
                g_h[(size_t)78 * NP + p] = __float2half(a7v * m);
                g_h[(size_t)79 * NP + p] = __float2half(a5v * m);
                g_h[(size_t)80 * NP + p] = __float2half(a3v * m);
                g_scratch[(size_t)6 * NP + p] = (1.0f - sumg) * dv + a1v * m;
            }
        }
    }
}

// ---------------- fused iteration (R11 exact: 2 px/thread, fp16 streams) ----------------
__device__ __constant__ const int G7DY[24] = {3,3,3,3,3,3,3, 2,2, 1,1, 0,0, -1,-1, -2,-2, -3,-3,-3,-3,-3,-3,-3};
__device__ __constant__ const int G7DX[24] = {3,2,1,0,-1,-2,-3, 3,-3, 3,-3, 3,-3, 3,-3, 3,-3, 3,2,1,0,-1,-2,-3};
__device__ __constant__ const int G5DY[16] = {2,2,2,2,2, 1,1, 0,0, -1,-1, -2,-2,-2,-2,-2};
__device__ __constant__ const int G5DX[16] = {2,1,0,-1,-2, 2,-2, 2,-2, 2,-2, 2,1,0,-1,-2};
__device__ __constant__ const int G3DY[8]  = {1,1,1, 0,0, -1,-1,-1};
__device__ __constant__ const int G3DX[8]  = {1,0,-1, 1,-1, 1,0,-1};

template <bool LAST>
__global__ void iter_fused(const float* __restrict__ d00, const float* __restrict__ d0,
                           float* __restrict__ out, int it, int rA, int wA,
                           int rBASE, int wBASE)
{
    int idx = blockIdx.x * 256 + threadIdx.x;
    int p0 = idx * 2;
    if (p0 >= NP) return;
    unsigned up = (unsigned)p0;
    int b = up / (unsigned)HW_;
    unsigned r = up - (unsigned)b * HW_;
    int y  = r / (unsigned)W_;
    int x0 = r - (unsigned)y * W_;

    const __half* AF  = g_h;
    const __half* A7p = g_h + (size_t)(rA + 0) * NP;
    const __half* A5p = g_h + (size_t)(rA + 1) * NP;
    const __half* A3p = g_h + (size_t)(rA + 2) * NP;

    float2 base = *reinterpret_cast<const float2*>(g_scratch + (size_t)rBASE * NP + p0);
    float acc0 = base.x, acc1 = base.y;

    const bool interior = (y >= 3) & (y < H_ - 3) & (x0 >= 3) & (x0 + 1 < W_ - 3);
    if (interior) {
        #pragma unroll
        for (int t = 0; t < 24; ++t) {
            const int dy = G7DY[t], dx = G7DX[t];
            int qq = p0 + dy * W_ + dx;
            const __half* fp = AF + (size_t)t * NP + qq;
            if ((dx & 1) == 0) {
                float2 f = __half22float2(*reinterpret_cast<const __half2*>(fp));
                float2 a = __half22float2(*reinterpret_cast<const __half2*>(A7p + qq));
                acc0 = fmaf(f.x, a.x, acc0);
                acc1 = fmaf(f.y, a.y, acc1);
            } else {
                acc0 = fmaf(__half2float(fp[0]), __half2float(A7p[qq]),     acc0);
                acc1 = fmaf(__half2float(fp[1]), __half2float(A7p[qq + 1]), acc1);
            }
        }
        #pragma unroll
        for (int t = 0; t < 16; ++t) {
            const int dy = G5DY[t], dx = G5DX[t];
            int qq = p0 + dy * W_ + dx;
            const __half* fp = AF + (size_t)(24 + t) * NP + qq;
            if ((dx & 1) == 0) {
                float2 f = __half22float2(*reinterpret_cast<const __half2*>(fp));
                float2 a = __half22float2(*reinterpret_cast<const __half2*>(A5p + qq));
                acc0 = fmaf(f.x, a.x, acc0);
                acc1 = fmaf(f.y, a.y, acc1);
            } else {
                acc0 = fmaf(__half2float(fp[0]), __half2float(A5p[qq]),     acc0);
                acc1 = fmaf(__half2float(fp[1]), __half2float(A5p[qq + 1]), acc1);
            }
        }
        #pragma unroll
        for (int t = 0; t < 8; ++t) {
            const int dy = G3DY[t], dx = G3DX[t];
            int qq = p0 + dy * W_ + dx;
            const __half* fp = AF + (size_t)(40 + t) * NP + qq;
            if ((dx & 1) == 0) {
                float2 f = __half22float2(*reinterpret_cast<const __half2*>(fp));
                float2 a = __half22float2(*reinterpret_cast<const __half2*>(A3p + qq));
                acc0 = fmaf(f.x, a.x, acc0);
                acc1 = fmaf(f.y, a.y, acc1);
            } else {
                acc0 = fmaf(__half2float(fp[0]), __half2float(A3p[qq]),     acc0);
                acc1 = fmaf(__half2float(fp[1]), __half2float(A3p[qq + 1]), acc1);
            }
        }
    } else {
        #pragma unroll
        for (int px = 0; px < 2; ++px) {
            const int xx = x0 + px;
            const int pp = p0 + px;
            float acc = (px == 0) ? acc0 : acc1;
            #pragma unroll
            for (int t = 0; t < 24; ++t) {
                const int dy = G7DY[t], dx = G7DX[t];
                if ((unsigned)(y + dy) < (unsigned)H_ && (unsigned)(xx + dx) < (unsigned)W_) {
                    int qq = pp + dy * W_ + dx;
                    acc = fmaf(__half2float(AF[(size_t)t * NP + qq]), __half2float(A7p[qq]), acc);
                }
            }
            #pragma unroll
            for (int t = 0; t < 16; ++t) {
                const int dy = G5DY[t], dx = G5DX[t];
                if ((unsigned)(y + dy) < (unsigned)H_ && (unsigned)(xx + dx) < (unsigned)W_) {
                    int qq = pp + dy * W_ + dx;
                    acc = fmaf(__half2float(AF[(size_t)(24 + t) * NP + qq]), __half2float(A5p[qq]), acc);
                }
            }
            #pragma unroll
            for (int t = 0; t < 8; ++t) {
                const int dy = G3DY[t], dx = G3DX[t];
                if ((unsigned)(y + dy) < (unsigned)H_ && (unsigned)(xx + dx) < (unsigned)W_) {
                    int qq = pp + dy * W_ + dx;
                    acc = fmaf(__half2float(AF[(size_t)(40 + t) * NP + qq]), __half2float(A3p[qq]), acc);
                }
            }
            if (px == 0) acc0 = acc; else acc1 = acc;
        }
    }

    float2 mk   = *reinterpret_cast<const float2*>(g_scratch + (size_t)it * NP + p0);
    float2 dd00 = *reinterpret_cast<const float2*>(d00 + p0);
    float dt0 = mk.x * dd00.x + (1.0f - mk.x) * acc0;
    float dt1 = mk.y * dd00.y + (1.0f - mk.y) * acc1;

    if (LAST) {
        *reinterpret_cast<float2*>(out + p0) = make_float2(dt0, dt1);
    } else {
        const int nit = it + 1;
        float2 a7 = __half22float2(*reinterpret_cast<const __half2*>(g_h + (size_t)(48 + nit) * NP + p0));
        float2 a5 = __half22float2(*reinterpret_cast<const __half2*>(g_h + (size_t)(54 + nit) * NP + p0));
        float2 a3 = __half22float2(*reinterpret_cast<const __half2*>(g_h + (size_t)(60 + nit) * NP + p0));
        float2 a1 = __half22float2(*reinterpret_cast<const __half2*>(g_h + (size_t)(66 + nit) * NP + p0));
        float2 s7 = __half22float2(*reinterpret_cast<const __half2*>(g_h + (size_t)72 * NP + p0));
        float2 s5 = __half22float2(*reinterpret_cast<const __half2*>(g_h + (size_t)73 * NP + p0));
        float2 s3 = __half22float2(*reinterpret_cast<const __half2*>(g_h + (size_t)74 * NP + p0));
        float2 t7 = __half22float2(*reinterpret_cast<const __half2*>(g_h + (size_t)75 * NP + p0));
        float2 t5 = __half22float2(*reinterpret_cast<const __half2*>(g_h + (size_t)76 * NP + p0));
        float2 t3 = __half22float2(*reinterpret_cast<const __half2*>(g_h + (size_t)77 * NP + p0));
        float2 dd0 = *reinterpret_cast<const float2*>(d0 + p0);

        float den0 = fmaf(a7.x, s7.x, fmaf(a5.x, s5.x, fmaf(a3.x, s3.x, a1.x)));
        float den1 = fmaf(a7.y, s7.y, fmaf(a5.y, s5.y, fmaf(a3.y, s3.y, a1.y)));
        float iv0 = 1.0f / den0, iv1 = 1.0f / den1;
        float sg0 = iv0 * fmaf(a7.x, t7.x, fmaf(a5.x, t5.x, fmaf(a3.x, t3.x, a1.x)));
        float sg1 = iv1 * fmaf(a7.y, t7.y, fmaf(a5.y, t5.y, fmaf(a3.y, t3.y, a1.y)));
        float m0 = iv0 * dt0, m1 = iv1 * dt1;

        *reinterpret_cast<__half2*>(g_h + (size_t)(wA + 0) * NP + p0) = __floats2half2_rn(a7.x * m0, a7.y * m1);
        *reinterpret_cast<__half2*>(g_h + (size_t)(wA + 1) * NP + p0) = __floats2half2_rn(a5.x * m0, a5.y * m1);
        *reinterpret_cast<__half2*>(g_h + (size_t)(wA + 2) * NP + p0) = __floats2half2_rn(a3.x * m0, a3.y * m1);
        float b0 = (1.0f - sg0) * dd0.x + a1.x * m0;
        float b1 = (1.0f - sg1) * dd0.y + a1.y * m1;
        *reinterpret_cast<float2*>(g_scratch + (size_t)wBASE * NP + p0) = make_float2(b0, b1);
    }
}

// ---------------- launch ----------------
extern "C" void kernel_launch(void* const* d_in, const int* in_sizes, int n_in,
                              void* d_out, int out_size)
{
    const float* feat = (const float*)d_in[0];
    const float* d0   = (const float*)d_in[1];
    const float* d00  = (const float*)d_in[2];

    cudaFuncSetAttribute(conv_kernel, cudaFuncAttributeMaxDynamicSharedMemorySize,
                         CONV_SMEM);

    pack_weights<<<(NCH * 576 + 255) / 256, 256>>>(
        (const float*)d_in[3],  (const float*)d_in[4],  (const float*)d_in[5],
        (const float*)d_in[6],  (const float*)d_in[7],  (const float*)d_in[8],
        (const float*)d_in[9],  (const float*)d_in[10], (const float*)d_in[11],
        (const float*)d_in[12], (const float*)d_in[13], (const float*)d_in[14],
        (const float*)d_in[15], (const float*)d_in[16], (const float*)d_in[17],
        (const float*)d_in[18], (const float*)d_in[19], (const float*)d_in[20],
        (const float*)d_in[21], (const float*)d_in[22], (const float*)d_in[23],
        (const float*)d_in[24], (const float*)d_in[25], (const float*)d_in[26]);

    pack_frags<<<(36 * 10 * 32 + 255) / 256, 256>>>();

    // shift conv into ncu capture slot 5 (launches 2,3,4 are no-ops)
    noopk<<<1, 32>>>();
    noopk<<<1, 32>>>();
    noopk<<<1, 32>>>();

    conv_kernel<<<dim3(19, H_ / 4, B_), 256, CONV_SMEM>>>(feat, d00, d0);

    const int nblk2 = NP / 512;  // 1216 exact
    for (int it = 0; it < ITERS; ++it) {
        const int rA = 78 + (it & 1) * 3;
        const int wA = 78 + ((it + 1) & 1) * 3;
        const int rB = 6 + (it & 1);
        const int wB = 6 + ((it + 1) & 1);
        if (it == ITERS - 1)
            iter_fused<true><<<nblk2, 256>>>(d00, d0, (float*)d_out, it, rA, wA, rB, wB);
        else
            iter_fused<false><<<nblk2, 256>>>(d00, d0, nullptr, it, rA, wA, rB, wB);
    }
}